// round 14
// baseline (speedup 1.0000x reference)
#include <cuda_runtime.h>
#include <cuda_fp16.h>
#include <cstdint>

#define NODES_TOTAL 100000
#define NNODES      20000
#define TN          50
#define INF         256
#define HIDF        256
#define OUTF        256
#define CATF        512

// Scratch (static __device__ arrays: allocation-free per harness rules)
__device__ __align__(16) __half g_qh[(size_t)NODES_TOTAL * HIDF];  // 51.2 MB (L2-resident)
__device__ __align__(16) __half g_cat[(size_t)NNODES * CATF];      // 20.5 MB
__device__ __align__(16) __half g_qw16[INF * HIDF];                // Qw in fp16
__device__ __align__(16) __half g_ww16[OUTF * CATF];               // Ww in fp16

// ---------------------------------------------------------------------------
// helpers
// ---------------------------------------------------------------------------
__device__ __forceinline__ void mma_f16_f32acc(float c[4], const uint32_t a[4],
                                               uint32_t b0, uint32_t b1) {
    asm volatile("mma.sync.aligned.m16n8k16.row.col.f32.f16.f16.f32 "
                 "{%0,%1,%2,%3}, {%4,%5,%6,%7}, {%8,%9}, {%0,%1,%2,%3};"
                 : "+f"(c[0]), "+f"(c[1]), "+f"(c[2]), "+f"(c[3])
                 : "r"(a[0]), "r"(a[1]), "r"(a[2]), "r"(a[3]), "r"(b0), "r"(b1));
}

__device__ __forceinline__ void ldmatrix_x4(uint32_t r[4], uint32_t saddr) {
    asm volatile("ldmatrix.sync.aligned.m8n8.x4.shared.b16 {%0,%1,%2,%3}, [%4];"
                 : "=r"(r[0]), "=r"(r[1]), "=r"(r[2]), "=r"(r[3]) : "r"(saddr));
}

__device__ __forceinline__ uint32_t pack_h2(float x, float y) {
    __half2 h = __float22half2_rn(make_float2(x, y));
    return *(uint32_t*)&h;
}

__device__ __forceinline__ void cp_async16(void* smem_dst, const void* gmem_src, bool pred) {
    uint32_t saddr = (uint32_t)__cvta_generic_to_shared(smem_dst);
    int sz = pred ? 16 : 0;
    asm volatile("cp.async.cg.shared.global [%0], [%1], 16, %2;"
                 :: "r"(saddr), "l"(gmem_src), "r"(sz));
}
#define CP_COMMIT() asm volatile("cp.async.commit_group;")
#define CP_WAIT0()  asm volatile("cp.async.wait_group 0;")
#define CP_WAIT1()  asm volatile("cp.async.wait_group 1;")

#define SROWH 40   // smem row stride in halves (80B -> conflict-free ldmatrix)

// ---------------------------------------------------------------------------
// k0: one-shot weight conversion fp32 -> fp16 (RN, identical rounding to the
// previous in-GEMM conversion).
// ---------------------------------------------------------------------------
__global__ __launch_bounds__(256) void cvt_weights_kernel(
    const float* __restrict__ Qw, const float* __restrict__ Ww)
{
    const int i = blockIdx.x * 256 + threadIdx.x;
    if (i < 16384) {
        const float4 v = ((const float4*)Qw)[i];
        ((uint2*)g_qw16)[i] = make_uint2(pack_h2(v.x, v.y), pack_h2(v.z, v.w));
    } else if (i < 49152) {
        const int j = i - 16384;
        const float4 v = ((const float4*)Ww)[j];
        ((uint2*)g_ww16)[j] = make_uint2(pack_h2(v.x, v.y), pack_h2(v.z, v.w));
    }
}

// ===========================================================================
// GEMM-A: QH[m0..m0+63, 0..255] = relu( h @ Qw^T + Qb ), fp16 out. K=256.
// CTA tile 64x256 (full N), 8 warps of 32x64. A fp32: register prefetch +
// cvt at STS (double buffer). B fp16: 3-stage cp.async ring, wait_group 1 ->
// the awaited group was issued two chunks earlier (copy latency fully hidden
// behind ~2 compute phases). One __syncthreads per chunk.
// smem = 2*(64*40) + 3*(256*40) halves = 71680 B -> 2 CTAs/SM.
// ===========================================================================
#define GA_SMEM ((2 * 64 * SROWH + 3 * 256 * SROWH) * 2)

__global__ __launch_bounds__(256, 2) void gemm_a_kernel(
    const float* __restrict__ A, const __half* __restrict__ B,
    const float* __restrict__ bias, __half* __restrict__ C, int M)
{
    extern __shared__ __half dsm[];
    __half* sA0 = dsm;                       // 64 x SROWH
    __half* sA1 = dsm + 64 * SROWH;
    __half* sBr = dsm + 2 * 64 * SROWH;      // ring: 3 stages of 256 x SROWH

    const int tid  = threadIdx.x;
    const int warp = tid >> 5;
    const int lane = tid & 31;
    const int g    = lane >> 2;
    const int tg   = lane & 3;
    const int m0   = (int)blockIdx.x * 64;
    const int wm   = (warp >> 2) * 32;
    const int wn   = (warp & 3) * 64;

    const int arow = tid >> 2;
    const int acol = (tid & 3) * 8;
    const bool va  = (m0 + arow) < M;

    float acc[2][8][4];
    #pragma unroll
    for (int i = 0; i < 2; i++)
        #pragma unroll
        for (int j = 0; j < 8; j++)
            #pragma unroll
            for (int r = 0; r < 4; r++) acc[i][j][r] = 0.f;

    // ---- prologue: B stages 0,1 async; A chunk 0 sync ----
    #pragma unroll
    for (int s = 0; s < 2; s++) {
        __half* dB = sBr + s * 256 * SROWH;
        #pragma unroll
        for (int t = 0; t < 4; t++) {
            const int i  = tid + t * 256;
            const int br = i >> 2, bg = (i & 3) * 8;
            cp_async16(&dB[br * SROWH + bg], B + (size_t)br * 256 + s * 32 + bg, true);
        }
        CP_COMMIT();
    }
    {
        float4 v0 = va ? *(const float4*)(A + (size_t)(m0 + arow) * 256 + acol)
                       : make_float4(0.f, 0.f, 0.f, 0.f);
        float4 v1 = va ? *(const float4*)(A + (size_t)(m0 + arow) * 256 + acol + 4)
                       : make_float4(0.f, 0.f, 0.f, 0.f);
        *(uint4*)&sA0[arow * SROWH + acol] =
            make_uint4(pack_h2(v0.x, v0.y), pack_h2(v0.z, v0.w),
                       pack_h2(v1.x, v1.y), pack_h2(v1.z, v1.w));
    }
    CP_WAIT1();        // stage 0 complete (stage 1 may be in flight)
    __syncthreads();

    const uint32_t uA0  = (uint32_t)__cvta_generic_to_shared(sA0);
    const uint32_t uA1  = (uint32_t)__cvta_generic_to_shared(sA1);
    const uint32_t uBrg = (uint32_t)__cvta_generic_to_shared(sBr);
    const uint32_t offA = (uint32_t)(((lane & 15) * SROWH + (lane >> 4) * 8) * 2);
    const uint32_t offB = (uint32_t)((((lane >> 4) * 8 + (lane & 7)) * SROWH
                                      + ((lane >> 3) & 1) * 8) * 2);

    #pragma unroll 1
    for (int c = 0; c < 8; c++) {
        // issue B stage c+2 (ring slot (c+2)%3: its readers drained at c-1)
        if (c + 2 < 8) {
            const int kk = (c + 2) * 32;
            __half* dB = sBr + ((c + 2) % 3) * 256 * SROWH;
            #pragma unroll
            for (int t = 0; t < 4; t++) {
                const int i  = tid + t * 256;
                const int br = i >> 2, bg = (i & 3) * 8;
                cp_async16(&dB[br * SROWH + bg], B + (size_t)br * 256 + kk + bg, true);
            }
            CP_COMMIT();
        }
        // reg-prefetch A chunk c+1
        float4 pa0, pa1;
        if (c < 7) {
            const int kk = (c + 1) * 32;
            pa0 = va ? *(const float4*)(A + (size_t)(m0 + arow) * 256 + kk + acol)
                     : make_float4(0.f, 0.f, 0.f, 0.f);
            pa1 = va ? *(const float4*)(A + (size_t)(m0 + arow) * 256 + kk + acol + 4)
                     : make_float4(0.f, 0.f, 0.f, 0.f);
        }

        // compute chunk c
        const uint32_t ubA = (c & 1) ? uA1 : uA0;
        const uint32_t ubB = uBrg + (uint32_t)((c % 3) * 256 * SROWH * 2);
        #pragma unroll
        for (int ks = 0; ks < 2; ks++) {
            uint32_t af[2][4];
            #pragma unroll
            for (int mf = 0; mf < 2; mf++)
                ldmatrix_x4(af[mf], ubA + offA
                            + (uint32_t)(((wm + mf * 16) * SROWH + ks * 16) * 2));
            uint32_t bf[4][4];
            #pragma unroll
            for (int p = 0; p < 4; p++)
                ldmatrix_x4(bf[p], ubB + offB
                            + (uint32_t)(((wn + p * 16) * SROWH + ks * 16) * 2));
            #pragma unroll
            for (int mf = 0; mf < 2; mf++)
                #pragma unroll
                for (int nf = 0; nf < 8; nf++)
                    mma_f16_f32acc(acc[mf][nf], af[mf], bf[nf >> 1][(nf & 1) * 2],
                                   bf[nf >> 1][(nf & 1) * 2 + 1]);
        }

        // store prefetched A; await B stage c+1; swap
        if (c < 7) {
            __half* dA = ((c + 1) & 1) ? sA1 : sA0;
            *(uint4*)&dA[arow * SROWH + acol] =
                make_uint4(pack_h2(pa0.x, pa0.y), pack_h2(pa0.z, pa0.w),
                           pack_h2(pa1.x, pa1.y), pack_h2(pa1.z, pa1.w));
            CP_WAIT1();
        }
        __syncthreads();
    }

    // ---- epilogue: bias + relu, fp16 store (row stride 256) ----
    #pragma unroll
    for (int mf = 0; mf < 2; mf++) {
        #pragma unroll
        for (int half = 0; half < 2; half++) {
            const int m = m0 + wm + mf * 16 + g + half * 8;
            if (m < M) {
                #pragma unroll
                for (int nf = 0; nf < 8; nf++) {
                    const int cc = wn + nf * 8 + tg * 2;
                    const float v0 = fmaxf(acc[mf][nf][half * 2 + 0] + __ldg(&bias[cc]),     0.f);
                    const float v1 = fmaxf(acc[mf][nf][half * 2 + 1] + __ldg(&bias[cc + 1]), 0.f);
                    *(uint32_t*)(C + (size_t)m * 256 + cc) = pack_h2(v0, v1);
                }
            }
        }
    }
}

// ===========================================================================
// GEMM-C + fused L2 norm: out[m0..m0+63, :] =
//   normalize( relu( g_cat @ Ww^T + Wb ) ).  K=512, full N=256 per CTA.
// Both operands fp16 -> 3-stage cp.async ring (A+B per stage), wait_group 1.
// 8 warps of 32x64. Epilogue: relu in regs -> per-row sumsq (quad shfl +
// smem atomics) -> rsqrt scale -> single fp32 store. 313 CTAs, 2 CTAs/SM.
// smem = 3*(64+256)*40 halves + 64 floats = 77056 B.
// ===========================================================================
#define GC_STAGEH ((64 + 256) * SROWH)          // halves per ring stage
#define GC_SMEM   (3 * GC_STAGEH * 2 + 256)

__global__ __launch_bounds__(256, 2) void gemm_c_kernel(
    const __half* __restrict__ A, const __half* __restrict__ B,
    const float* __restrict__ bias, float* __restrict__ C, int M)
{
    extern __shared__ __half dsm[];
    float* s_ss = (float*)(dsm + 3 * GC_STAGEH);   // [64] per-row sumsq

    const int tid  = threadIdx.x;
    const int warp = tid >> 5;
    const int lane = tid & 31;
    const int g    = lane >> 2;
    const int tg   = lane & 3;
    const int m0   = (int)blockIdx.x * 64;
    const int wm   = (warp >> 2) * 32;
    const int wn   = (warp & 3) * 64;
    const int K    = 512;

    // A: 64 rows x 32 halves -> 1 granule/thread; B: 256 rows -> 4/thread
    const int ar = tid >> 2, ag = (tid & 3) * 8;
    const bool va = (m0 + ar) < M;

    float acc[2][8][4];
    #pragma unroll
    for (int i = 0; i < 2; i++)
        #pragma unroll
        for (int j = 0; j < 8; j++)
            #pragma unroll
            for (int r = 0; r < 4; r++) acc[i][j][r] = 0.f;

    if (tid < 64) s_ss[tid] = 0.f;

    // ---- prologue: async-stage ring slots 0,1 ----
    #pragma unroll
    for (int s = 0; s < 2; s++) {
        __half* dA = dsm + s * GC_STAGEH;
        __half* dB = dA + 64 * SROWH;
        cp_async16(&dA[ar * SROWH + ag], A + (size_t)(m0 + ar) * K + s * 32 + ag, va);
        #pragma unroll
        for (int t = 0; t < 4; t++) {
            const int i  = tid + t * 256;
            const int br = i >> 2, bg = (i & 3) * 8;
            cp_async16(&dB[br * SROWH + bg], B + (size_t)br * K + s * 32 + bg, true);
        }
        CP_COMMIT();
    }
    CP_WAIT1();
    __syncthreads();

    const uint32_t uRing = (uint32_t)__cvta_generic_to_shared(dsm);
    const uint32_t offA  = (uint32_t)(((lane & 15) * SROWH + (lane >> 4) * 8) * 2);
    const uint32_t offB  = (uint32_t)((((lane >> 4) * 8 + (lane & 7)) * SROWH
                                       + ((lane >> 3) & 1) * 8) * 2);

    #pragma unroll 1
    for (int c = 0; c < 16; c++) {
        if (c + 2 < 16) {
            const int kk = (c + 2) * 32;
            __half* dA = dsm + ((c + 2) % 3) * GC_STAGEH;
            __half* dB = dA + 64 * SROWH;
            cp_async16(&dA[ar * SROWH + ag], A + (size_t)(m0 + ar) * K + kk + ag, va);
            #pragma unroll
            for (int t = 0; t < 4; t++) {
                const int i  = tid + t * 256;
                const int br = i >> 2, bg = (i & 3) * 8;
                cp_async16(&dB[br * SROWH + bg], B + (size_t)br * K + kk + bg, true);
            }
            CP_COMMIT();
        }

        const uint32_t uS  = uRing + (uint32_t)((c % 3) * GC_STAGEH * 2);
        const uint32_t ubA = uS;
        const uint32_t ubB = uS + (uint32_t)(64 * SROWH * 2);
        #pragma unroll
        for (int ks = 0; ks < 2; ks++) {
            uint32_t af[2][4];
            #pragma unroll
            for (int mf = 0; mf < 2; mf++)
                ldmatrix_x4(af[mf], ubA + offA
                            + (uint32_t)(((wm + mf * 16) * SROWH + ks * 16) * 2));
            uint32_t bf[4][4];
            #pragma unroll
            for (int p = 0; p < 4; p++)
                ldmatrix_x4(bf[p], ubB + offB
                            + (uint32_t)(((wn + p * 16) * SROWH + ks * 16) * 2));
            #pragma unroll
            for (int mf = 0; mf < 2; mf++)
                #pragma unroll
                for (int nf = 0; nf < 8; nf++)
                    mma_f16_f32acc(acc[mf][nf], af[mf], bf[nf >> 1][(nf & 1) * 2],
                                   bf[nf >> 1][(nf & 1) * 2 + 1]);
        }

        if (c + 1 < 16) CP_WAIT1();
        __syncthreads();
    }

    // ---- epilogue: relu in regs, fused per-row L2 norm, fp32 store ----
    float ss[2][2];
    #pragma unroll
    for (int mf = 0; mf < 2; mf++)
        #pragma unroll
        for (int half = 0; half < 2; half++) {
            float s = 0.f;
            #pragma unroll
            for (int nf = 0; nf < 8; nf++) {
                const int cc = wn + nf * 8 + tg * 2;
                float v0 = fmaxf(acc[mf][nf][half * 2 + 0] + __ldg(&bias[cc]),     0.f);
                float v1 = fmaxf(acc[mf][nf][half * 2 + 1] + __ldg(&bias[cc + 1]), 0.f);
                acc[mf][nf][half * 2 + 0] = v0;
                acc[mf][nf][half * 2 + 1] = v1;
                s += v0 * v0 + v1 * v1;
            }
            ss[mf][half] = s;
        }
    // reduce over the 4-lane quad (lane bits 0,1 = tg)
    #pragma unroll
    for (int mf = 0; mf < 2; mf++)
        #pragma unroll
        for (int half = 0; half < 2; half++) {
            ss[mf][half] += __shfl_xor_sync(0xffffffffu, ss[mf][half], 1);
            ss[mf][half] += __shfl_xor_sync(0xffffffffu, ss[mf][half], 2);
        }
    if (tg == 0) {
        #pragma unroll
        for (int mf = 0; mf < 2; mf++)
            #pragma unroll
            for (int half = 0; half < 2; half++)
                atomicAdd(&s_ss[wm + mf * 16 + g + half * 8], ss[mf][half]);
    }
    __syncthreads();

    #pragma unroll
    for (int mf = 0; mf < 2; mf++)
        #pragma unroll
        for (int half = 0; half < 2; half++) {
            const int r = wm + mf * 16 + g + half * 8;
            const int m = m0 + r;
            if (m < M) {
                const float inv = rsqrtf(s_ss[r]);
                #pragma unroll
                for (int nf = 0; nf < 8; nf++) {
                    const int cc = wn + nf * 8 + tg * 2;
                    *(float2*)(C + (size_t)m * 256 + cc) =
                        make_float2(acc[mf][nf][half * 2 + 0] * inv,
                                    acc[mf][nf][half * 2 + 1] * inv);
                }
            }
        }
}

// ---------------------------------------------------------------------------
// Aggregation: h_agg[n] = sum_t w[n,t]*QH[nb[n,t]] / sum_t w[n,t]
// QH fp16 (L2-resident; at the chip LTS gather floor). One warp per node;
// also copies h[nodeset[n]] (fp32->fp16) into the first half of g_cat row.
// ---------------------------------------------------------------------------
__global__ __launch_bounds__(256) void agg_kernel(
    const float* __restrict__ h, const int* __restrict__ nodeset,
    const int* __restrict__ nb_nodes, const float* __restrict__ nb_w)
{
    __shared__ int   s_idx[8][TN];
    __shared__ float s_w[8][TN];

    const int tid  = threadIdx.x;
    const int warp = tid >> 5;
    const int lane = tid & 31;
    const int n    = blockIdx.x * 8 + warp;   // 20000/8 = 2500 blocks exact

    for (int j = lane; j < TN; j += 32) {
        s_idx[warp][j] = nb_nodes[n * TN + j];
        s_w[warp][j]   = nb_w[n * TN + j];
    }
    __syncwarp();

    float wsum = 0.f;
    #pragma unroll
    for (int t = 0; t < TN; t++) wsum += s_w[warp][t];   // smem broadcast

    const int colb = lane * 8;
    float acc[8];
    #pragma unroll
    for (int i = 0; i < 8; i++) acc[i] = 0.f;

    #pragma unroll 10
    for (int t = 0; t < TN; t++) {
        const int   idx = s_idx[warp][t];
        const float w   = s_w[warp][t];
        union { uint4 u; __half2 h2[4]; } q;
        q.u = *(const uint4*)(g_qh + (size_t)idx * HIDF + colb);
        #pragma unroll
        for (int i = 0; i < 4; i++) {
            const float2 f = __half22float2(q.h2[i]);
            acc[2 * i]     += w * f.x;
            acc[2 * i + 1] += w * f.y;
        }
    }
    const float inv = 1.f / wsum;
    union { uint4 u; __half2 h2[4]; } o;
    #pragma unroll
    for (int i = 0; i < 4; i++)
        o.h2[i] = __float22half2_rn(make_float2(acc[2 * i] * inv, acc[2 * i + 1] * inv));
    *(uint4*)(g_cat + (size_t)n * CATF + INF + colb) = o.u;

    const int self = nodeset[n];
    const float4 s0 = *(const float4*)(h + (size_t)self * INF + colb);
    const float4 s1 = *(const float4*)(h + (size_t)self * INF + colb + 4);
    union { uint4 u; __half2 h2[4]; } sc;
    sc.h2[0] = __float22half2_rn(make_float2(s0.x, s0.y));
    sc.h2[1] = __float22half2_rn(make_float2(s0.z, s0.w));
    sc.h2[2] = __float22half2_rn(make_float2(s1.x, s1.y));
    sc.h2[3] = __float22half2_rn(make_float2(s1.z, s1.w));
    *(uint4*)(g_cat + (size_t)n * CATF + colb) = sc.u;
}

// ---------------------------------------------------------------------------
extern "C" void kernel_launch(void* const* d_in, const int* in_sizes, int n_in,
                              void* d_out, int out_size)
{
    const float* h        = (const float*)d_in[0];
    const int*   nodeset  = (const int*)d_in[1];
    const int*   nb_nodes = (const int*)d_in[2];
    const float* nb_w     = (const float*)d_in[3];
    const float* Qw       = (const float*)d_in[4];
    const float* Qb       = (const float*)d_in[5];
    const float* Ww       = (const float*)d_in[6];
    const float* Wb       = (const float*)d_in[7];
    float*       out      = (float*)d_out;

    __half* qh   = nullptr;
    __half* cat  = nullptr;
    __half* qw16 = nullptr;
    __half* ww16 = nullptr;
    cudaGetSymbolAddress((void**)&qh,   g_qh);
    cudaGetSymbolAddress((void**)&cat,  g_cat);
    cudaGetSymbolAddress((void**)&qw16, g_qw16);
    cudaGetSymbolAddress((void**)&ww16, g_ww16);

    static bool attr_done = false;
    if (!attr_done) {
        cudaFuncSetAttribute(gemm_a_kernel,
                             cudaFuncAttributeMaxDynamicSharedMemorySize, GA_SMEM);
        cudaFuncSetAttribute(gemm_c_kernel,
                             cudaFuncAttributeMaxDynamicSharedMemorySize, GC_SMEM);
        attr_done = true;
    }

    // k0: weights -> fp16 (once per launch; ~2us)
    cvt_weights_kernel<<<192, 256>>>(Qw, Ww);

    // k1: QH = relu(h @ Qw^T + Qb) -> fp16 [100000, 256]
    {
        const int tilesM = (NODES_TOTAL + 63) / 64;   // 1563
        gemm_a_kernel<<<tilesM, 256, GA_SMEM>>>(h, qw16, Qb, qh, NODES_TOTAL);
    }
    // k2: aggregate + self gather -> g_cat fp16 [20000, 512]
    agg_kernel<<<NNODES / 8, 256>>>(h, nodeset, nb_nodes, nb_w);

    // k3: out = normalize(relu(g_cat @ Ww^T + Wb))  [20000, 256] (norm fused)
    {
        const int tilesM = (NNODES + 63) / 64;        // 313
        gemm_c_kernel<<<tilesM, 256, GC_SMEM>>>(cat, ww16, Wb, out, NNODES);
    }
}